// round 16
// baseline (speedup 1.0000x reference)
#include <cuda_runtime.h>
#include <cuda_bf16.h>
#include <cuda_fp16.h>
#include <math.h>
#include <cstdint>

// Problem constants
#define B_    4
#define T_    8192
#define DIM_  1024
#define NH_   16
#define DH_   64
#define WIN_  128
#define NW_   (T_ / WIN_)          // 64
#define MTOT  (B_ * T_)            // 32768
#define GK    1024                 // GEMM K

extern __shared__ char dynsm[];

// ---------------------------------------------------------------------------
// Scratch
// ---------------------------------------------------------------------------
__device__ __half  g_Af [(size_t)MTOT * GK];        // LN out (fp16 single)
__device__ __half  g_Wf [(size_t)3 * DIM_ * GK];    // w_qkv fp16 single
__device__ __half  g_Wof[(size_t)DIM_ * GK];        // w_out fp16 single
__device__ float   g_qkv[(size_t)3 * DIM_ * MTOT];  // qkv (N,M)
__device__ __half  g_Cf [(size_t)MTOT * GK];        // ctx fp16 single
__device__ float   g_mean[MTOT];
__device__ float   g_rstd[MTOT];
__device__ float2  g_cs[32 * 128];                  // RoPE table

// ---------------------------------------------------------------------------
// PTX helpers
// ---------------------------------------------------------------------------
__device__ __forceinline__ uint32_t smem_u32(const void* p) {
    uint32_t a;
    asm("{ .reg .u64 t; cvta.to.shared.u64 t, %1; cvt.u32.u64 %0, t; }" : "=r"(a) : "l"(p));
    return a;
}
__device__ __forceinline__ void cp_async16(uint32_t dst, const void* src) {
    asm volatile("cp.async.cg.shared.global [%0], [%1], 16;" :: "r"(dst), "l"(src));
}
#define CP_COMMIT()  asm volatile("cp.async.commit_group;" ::: "memory")
#define CP_WAIT(n)   asm volatile("cp.async.wait_group %0;" :: "n"(n) : "memory")

__device__ __forceinline__ void ldsm_x4(uint32_t* r, uint32_t addr) {
    asm volatile("ldmatrix.sync.aligned.m8n8.x4.shared.b16 {%0,%1,%2,%3}, [%4];"
        : "=r"(r[0]), "=r"(r[1]), "=r"(r[2]), "=r"(r[3]) : "r"(addr));
}
__device__ __forceinline__ void ldsm_x2(uint32_t* r, uint32_t addr) {
    asm volatile("ldmatrix.sync.aligned.m8n8.x2.shared.b16 {%0,%1}, [%2];"
        : "=r"(r[0]), "=r"(r[1]) : "r"(addr));
}
__device__ __forceinline__ void ldsm_x4_t(uint32_t* r, uint32_t addr) {
    asm volatile("ldmatrix.sync.aligned.m8n8.x4.trans.shared.b16 {%0,%1,%2,%3}, [%4];"
        : "=r"(r[0]), "=r"(r[1]), "=r"(r[2]), "=r"(r[3]) : "r"(addr));
}
__device__ __forceinline__ void ldsm_x2_t(uint32_t* r, uint32_t addr) {
    asm volatile("ldmatrix.sync.aligned.m8n8.x2.trans.shared.b16 {%0,%1}, [%2];"
        : "=r"(r[0]), "=r"(r[1]) : "r"(addr));
}
__device__ __forceinline__ void mma_f16(float* d, const uint32_t* a, const uint32_t* b) {
    asm volatile("mma.sync.aligned.m16n8k16.row.col.f32.f16.f16.f32 "
        "{%0,%1,%2,%3}, {%4,%5,%6,%7}, {%8,%9}, {%0,%1,%2,%3};"
        : "+f"(d[0]), "+f"(d[1]), "+f"(d[2]), "+f"(d[3])
        : "r"(a[0]), "r"(a[1]), "r"(a[2]), "r"(a[3]), "r"(b[0]), "r"(b[1]));
}

__device__ __forceinline__ uint2 pack4h(const float* v) {
    __half2 h01 = __floats2half2_rn(v[0], v[1]);
    __half2 h23 = __floats2half2_rn(v[2], v[3]);
    uint2 r; r.x = *(uint32_t*)&h01; r.y = *(uint32_t*)&h23; return r;
}
__device__ __forceinline__ uint32_t pack2h(float v0, float v1) {
    __half2 h = __floats2half2_rn(v0, v1);
    return *(uint32_t*)&h;
}

// ---------------------------------------------------------------------------
// Kernel 1: LN statistics.
// ---------------------------------------------------------------------------
__global__ __launch_bounds__(256) void ln_stats_kernel(const float* __restrict__ x)
{
    const int lane = threadIdx.x & 31;
    const int wy   = threadIdx.x >> 5;
    const int b    = blockIdx.y;
    const int t    = blockIdx.x * 32 + lane;
    const size_t xbase = (size_t)b * DIM_ * T_ + t;

    float sum = 0.f, sum2 = 0.f;
    for (int c = wy; c < DIM_; c += 8) {
        float v = x[xbase + (size_t)c * T_];
        sum += v; sum2 += v * v;
    }
    __shared__ float ps[8][32], ps2[8][32];
    ps[wy][lane] = sum; ps2[wy][lane] = sum2;
    __syncthreads();
    if (wy == 0) {
        float s = 0.f, s2 = 0.f;
        #pragma unroll
        for (int i = 0; i < 8; ++i) { s += ps[i][lane]; s2 += ps2[i][lane]; }
        float mean = s * (1.f / DIM_);
        float var  = s2 * (1.f / DIM_) - mean * mean;
        g_mean[b * T_ + t] = mean;
        g_rstd[b * T_ + t] = rsqrtf(var + 1e-5f);
    }
}

// ---------------------------------------------------------------------------
// Kernel 2: transpose + normalize + fp16 convert.
// ---------------------------------------------------------------------------
__global__ __launch_bounds__(256) void ln_tsplit_kernel(
    const float* __restrict__ x,
    const float* __restrict__ ln_w,
    const float* __restrict__ ln_b)
{
    __shared__ float tile[32][33];
    const int lane = threadIdx.x & 31;
    const int wy   = threadIdx.x >> 5;
    const int t0 = blockIdx.x * 32;
    const int c0 = blockIdx.y * 32;
    const int b  = blockIdx.z;

    #pragma unroll
    for (int jj = 0; jj < 4; ++jj) {
        const int cl = wy * 4 + jj;
        tile[cl][lane] = x[(size_t)b * DIM_ * T_ + (size_t)(c0 + cl) * T_ + t0 + lane];
    }
    __syncthreads();

    const int c = c0 + lane;
    const float lw = ln_w[c], lb = ln_b[c];
    #pragma unroll
    for (int jj = 0; jj < 4; ++jj) {
        const int r = wy * 4 + jj;
        const int m = b * T_ + t0 + r;
        const float val = (tile[lane][r] - g_mean[m]) * g_rstd[m] * lw + lb;
        g_Af[(size_t)m * GK + c] = __float2half_rn(val);
    }
}

// ---------------------------------------------------------------------------
// Kernel 3: weight fp16 conversion + RoPE table fill.
// ---------------------------------------------------------------------------
#define NW1 (3 * DIM_ * GK)
#define NW2 (DIM_ * GK)
#define RKC 0.4152410118609203f   // log2(10000)/32

__global__ __launch_bounds__(256) void wsplit_kernel(
    const float* __restrict__ w1, const float* __restrict__ w2)
{
    const int i = blockIdx.x * 256 + threadIdx.x;
    if (i < NW1) {
        g_Wf[i] = __float2half_rn(w1[i]);
    } else if (i < NW1 + NW2) {
        g_Wof[i - NW1] = __float2half_rn(w2[i - NW1]);
    } else {
        const int e = i - (NW1 + NW2);
        const int d = e >> 7, tok = e & 127;
        const float ang = (float)tok * exp2f(-(float)d * RKC);
        float s, c;
        sincosf(ang, &s, &c);
        g_cs[e] = make_float2(c, s);
    }
}

// ---------------------------------------------------------------------------
// Kernel 4: single-pass fp16 GEMM, 4-stage cp.async pipeline, KC=32.
// ---------------------------------------------------------------------------
#define KC 32
#define NCHUNK (GK / KC)            // 32
#define STG1 16384                  // A 8K | B 8K
#define GEMM1P_SMEM (128 * 132 * 4) // 67584 (>= 4 stages = 64K; C staging union)

__device__ __forceinline__ void load_stage_1p(
    const __half* __restrict__ A, const __half* __restrict__ Bw,
    uint32_t sbase, int m0, int n0, int k0, int tid)
{
    #pragma unroll
    for (int it = 0; it < 2; ++it) {
        const int o = it * 256 + tid;
        const int r = o >> 2, q = o & 3;
        const uint32_t sw = (uint32_t)(r * 64 + ((q ^ ((r >> 1) & 3)) << 4));
        const size_t ga = (size_t)(m0 + r) * GK + k0 + q * 8;
        const size_t gb = (size_t)(n0 + r) * GK + k0 + q * 8;
        cp_async16(sbase + sw,        A  + ga);
        cp_async16(sbase + 8192 + sw, Bw + gb);
    }
}

__global__ __launch_bounds__(256) void gemm1p_kernel(
    const __half* __restrict__ A, const __half* __restrict__ Bw,
    float* __restrict__ C, const float* __restrict__ resid, int mode)
{
    const uint32_t smb = smem_u32(dynsm);
    const int tid  = threadIdx.x;
    const int wid  = tid >> 5;
    const int lane = tid & 31;
    const int wm = wid >> 2;
    const int wn = wid & 3;
    const int n0 = blockIdx.x * 128;
    const int m0 = blockIdx.y * 128;

    float acc[4][4][4];
    #pragma unroll
    for (int i = 0; i < 4; ++i)
        #pragma unroll
        for (int j = 0; j < 4; ++j)
            #pragma unroll
            for (int k = 0; k < 4; ++k) acc[i][j][k] = 0.f;

    // prologue: 3 stages in flight
    load_stage_1p(A, Bw, smb + 0 * STG1, m0, n0, 0 * KC, tid);
    CP_COMMIT();
    load_stage_1p(A, Bw, smb + 1 * STG1, m0, n0, 1 * KC, tid);
    CP_COMMIT();
    load_stage_1p(A, Bw, smb + 2 * STG1, m0, n0, 2 * KC, tid);
    CP_COMMIT();

    const int arow_l = (lane & 15);
    const int aq_l   = lane >> 4;
    const int brow_l = (lane & 7);
    const int bq_l   = (lane >> 3) & 1;

    for (int i = 0; i < NCHUNK; ++i) {
        if (i <= NCHUNK - 3)      CP_WAIT(2);
        else if (i == NCHUNK - 2) CP_WAIT(1);
        else                      CP_WAIT(0);
        __syncthreads();
        if (i + 3 < NCHUNK) {
            load_stage_1p(A, Bw, smb + ((i + 3) & 3) * STG1, m0, n0, (i + 3) * KC, tid);
            CP_COMMIT();
        }

        const uint32_t sA = smb + (i & 3) * STG1;
        #pragma unroll
        for (int ks = 0; ks < 2; ++ks) {
            uint32_t af[4][4], bh[4][2];
            #pragma unroll
            for (int mt = 0; mt < 4; ++mt) {
                const int row = wm * 64 + mt * 16 + arow_l;
                const int q   = ks * 2 + aq_l;
                ldsm_x4(af[mt], sA + row * 64 + ((q ^ ((row >> 1) & 3)) << 4));
            }
            #pragma unroll
            for (int nt = 0; nt < 4; ++nt) {
                const int row = wn * 32 + nt * 8 + brow_l;
                const int q   = ks * 2 + bq_l;
                ldsm_x2(bh[nt], sA + 8192 + row * 64 + ((q ^ ((row >> 1) & 3)) << 4));
            }
            #pragma unroll
            for (int mt = 0; mt < 4; ++mt)
                #pragma unroll
                for (int nt = 0; nt < 4; ++nt)
                    mma_f16(acc[mt][nt], af[mt], bh[nt]);
        }
    }
    __syncthreads();

    float* Cs = (float*)dynsm;
    const int g  = lane >> 2;
    const int tp = lane & 3;
    #pragma unroll
    for (int mt = 0; mt < 4; ++mt)
        #pragma unroll
        for (int nt = 0; nt < 4; ++nt) {
            const int mb = wm * 64 + mt * 16;
            const int nb = wn * 32 + nt * 8;
            Cs[(nb + 2 * tp)     * 132 + mb + g]     = acc[mt][nt][0];
            Cs[(nb + 2 * tp + 1) * 132 + mb + g]     = acc[mt][nt][1];
            Cs[(nb + 2 * tp)     * 132 + mb + g + 8] = acc[mt][nt][2];
            Cs[(nb + 2 * tp + 1) * 132 + mb + g + 8] = acc[mt][nt][3];
        }
    __syncthreads();

    if (mode == 0) {
        for (int o = tid; o < 128 * 128; o += 256) {
            const int r = o >> 7, c = o & 127;
            C[(size_t)(n0 + r) * MTOT + m0 + c] = Cs[r * 132 + c];
        }
    } else {
        const int b = m0 >> 13;
        const int t = m0 & (T_ - 1);
        const size_t base = (size_t)b * DIM_ * T_ + t;
        for (int o = tid; o < 128 * 128; o += 256) {
            const int r = o >> 7, c = o & 127;
            const size_t idx = base + (size_t)(n0 + r) * T_ + c;
            C[idx] = Cs[r * 132 + c] + resid[idx];
        }
    }
}

// ---------------------------------------------------------------------------
// Kernel 5: windowed attention, single-pass fp16 both MMAs.
// smem (52 KB):
//   [0,16K)Q [16K,32K)K  -- [d=64][tok=128] fp16   (overlaid by P [0,32K))
//   [32K,48K)V  -- [d][tok]
//   [48K,50K) pmax[128][4]  [50K,52K) psum[128][4]
// ---------------------------------------------------------------------------
#define AT_QF  0
#define AT_KF  16384
#define AT_PF  0
#define AT_VF  32768
#define AT_PMAX 49152
#define AT_PSUM 51200
#define ATTN_SMEM 53248

__global__ __launch_bounds__(256, 2) void attn_kernel(const float* __restrict__ qkv)
{
    const int blk = blockIdx.x;
    const int w   = blk & (NW_ - 1);
    const int hh  = (blk >> 6) & (NH_ - 1);
    const int b   = blk >> 10;
    const size_t M  = MTOT;
    const size_t m0 = (size_t)b * T_ + (size_t)w * WIN_;
    const int tid  = threadIdx.x;
    const int wid  = tid >> 5;
    const int lane = tid & 31;

    const uint32_t smb = smem_u32(dynsm);
    float* pmax = (float*)(dynsm + AT_PMAX);
    float* psum = (float*)(dynsm + AT_PSUM);

    // ---- phase 1: global load + RoPE; all fp16 single ----
    for (int it = tid; it < 512; it += 256) {
        const int d = it >> 4, ch = it & 15;
        const float* qp = qkv + (size_t)(hh * 64 + d) * M + m0 + ch * 8;
        float ql[8], qh[8], kl[8], kh[8], v0[8], v1[8];
        *(float4*)&ql[0] = *(const float4*)&qp[0];
        *(float4*)&ql[4] = *(const float4*)&qp[4];
        *(float4*)&qh[0] = *(const float4*)&qp[32 * M];
        *(float4*)&qh[4] = *(const float4*)&qp[32 * M + 4];
        const float* kp = qp + (size_t)DIM_ * M;
        *(float4*)&kl[0] = *(const float4*)&kp[0];
        *(float4*)&kl[4] = *(const float4*)&kp[4];
        *(float4*)&kh[0] = *(const float4*)&kp[32 * M];
        *(float4*)&kh[4] = *(const float4*)&kp[32 * M + 4];
        const float* vp = qp + (size_t)(2 * DIM_) * M;
        *(float4*)&v0[0] = *(const float4*)&vp[0];
        *(float4*)&v0[4] = *(const float4*)&vp[4];
        *(float4*)&v1[0] = *(const float4*)&vp[32 * M];
        *(float4*)&v1[4] = *(const float4*)&vp[32 * M + 4];

        float qnl[8], qnu[8], knl[8], knu[8];
        #pragma unroll
        for (int j = 0; j < 8; ++j) {
            const float2 cs = g_cs[d * 128 + ch * 8 + j];
            qnl[j] = ql[j] * cs.x - qh[j] * cs.y;
            qnu[j] = qh[j] * cs.x + ql[j] * cs.y;
            knl[j] = kl[j] * cs.x - kh[j] * cs.y;
            knu[j] = kh[j] * cs.x + kl[j] * cs.y;
        }
        const uint32_t swd  = (uint32_t)(d * 256 + ((ch ^ (d & 7)) << 4));
        const uint32_t swd2 = swd + 32 * 256;
        uint2 a0, a1;
        a0 = pack4h(&qnl[0]); a1 = pack4h(&qnl[4]);
        *(uint4*)(dynsm + AT_QF + swd) = make_uint4(a0.x, a0.y, a1.x, a1.y);
        a0 = pack4h(&qnu[0]); a1 = pack4h(&qnu[4]);
        *(uint4*)(dynsm + AT_QF + swd2) = make_uint4(a0.x, a0.y, a1.x, a1.y);
        a0 = pack4h(&knl[0]); a1 = pack4h(&knl[4]);
        *(uint4*)(dynsm + AT_KF + swd) = make_uint4(a0.x, a0.y, a1.x, a1.y);
        a0 = pack4h(&knu[0]); a1 = pack4h(&knu[4]);
        *(uint4*)(dynsm + AT_KF + swd2) = make_uint4(a0.x, a0.y, a1.x, a1.y);
        a0 = pack4h(&v0[0]); a1 = pack4h(&v0[4]);
        *(uint4*)(dynsm + AT_VF + swd) = make_uint4(a0.x, a0.y, a1.x, a1.y);
        a0 = pack4h(&v1[0]); a1 = pack4h(&v1[4]);
        *(uint4*)(dynsm + AT_VF + swd2) = make_uint4(a0.x, a0.y, a1.x, a1.y);
    }
    __syncthreads();

    // ---- phase 2: S = Q@K^T via trans-ldmatrix (single pass) ----
    const int g  = lane >> 2;
    const int tp = lane & 3;
    float acc[4][4][4];
    {
        const int wm = wid >> 2, wn = wid & 3;
        #pragma unroll
        for (int i = 0; i < 4; ++i)
            #pragma unroll
            for (int j = 0; j < 4; ++j)
                #pragma unroll
                for (int k = 0; k < 4; ++k) acc[i][j][k] = 0.f;

        const int Lg   = lane & 7;
        const int grpA = lane >> 3;
        const int aoff = ((grpA & 2) << 2) + Lg;
        const int acb  = wm * 8 + (grpA & 1);
        const int bg   = (lane >> 3) & 1;

        #pragma unroll
        for (int ks = 0; ks < 4; ++ks) {
            uint32_t af[4][4], bh[4][2];
            const uint32_t arow = (uint32_t)((ks * 16 + aoff) * 256);
            #pragma unroll
            for (int mt = 0; mt < 4; ++mt)
                ldsm_x4_t(af[mt], smb + AT_QF + arow + (((acb + mt * 2) ^ Lg) << 4));
            const uint32_t brow = (uint32_t)((ks * 16 + bg * 8 + Lg) * 256);
            #pragma unroll
            for (int nt = 0; nt < 4; ++nt)
                ldsm_x2_t(bh[nt], smb + AT_KF + brow + (((wn * 4 + nt) ^ Lg) << 4));
            #pragma unroll
            for (int mt = 0; mt < 4; ++mt)
                #pragma unroll
                for (int nt = 0; nt < 4; ++nt)
                    mma_f16(acc[mt][nt], af[mt], bh[nt]);
        }

        // ---- phase 3: softmax from registers ----
        #pragma unroll
        for (int mt = 0; mt < 4; ++mt)
            #pragma unroll
            for (int h = 0; h < 2; ++h) {
                float mx = -1e30f;
                #pragma unroll
                for (int nt = 0; nt < 4; ++nt)
                    mx = fmaxf(mx, fmaxf(acc[mt][nt][h * 2], acc[mt][nt][h * 2 + 1]));
                mx = fmaxf(mx, __shfl_xor_sync(0xffffffffu, mx, 1));
                mx = fmaxf(mx, __shfl_xor_sync(0xffffffffu, mx, 2));
                if (tp == 0)
                    pmax[(wm * 64 + mt * 16 + h * 8 + g) * 4 + wn] = mx;
            }
        __syncthreads();
        #pragma unroll
        for (int mt = 0; mt < 4; ++mt)
            #pragma unroll
            for (int h = 0; h < 2; ++h) {
                const int row = wm * 64 + mt * 16 + h * 8 + g;
                const float4 pm = *(const float4*)&pmax[row * 4];
                const float Mx = fmaxf(fmaxf(pm.x, pm.y), fmaxf(pm.z, pm.w));
                float s = 0.f;
                #pragma unroll
                for (int nt = 0; nt < 4; ++nt) {
                    float e0 = __expf((acc[mt][nt][h * 2]     - Mx) * 0.125f);
                    float e1 = __expf((acc[mt][nt][h * 2 + 1] - Mx) * 0.125f);
                    acc[mt][nt][h * 2]     = e0;
                    acc[mt][nt][h * 2 + 1] = e1;
                    s += e0 + e1;
                }
                s += __shfl_xor_sync(0xffffffffu, s, 1);
                s += __shfl_xor_sync(0xffffffffu, s, 2);
                if (tp == 0)
                    psum[(wm * 64 + mt * 16 + h * 8 + g) * 4 + wn] = s;
            }
        __syncthreads();
        #pragma unroll
        for (int mt = 0; mt < 4; ++mt)
            #pragma unroll
            for (int h = 0; h < 2; ++h) {
                const int row = wm * 64 + mt * 16 + h * 8 + g;
                const float4 sm4 = *(const float4*)&psum[row * 4];
                const float inv = 1.f / (sm4.x + sm4.y + sm4.z + sm4.w);
                #pragma unroll
                for (int nt = 0; nt < 4; ++nt) {
                    const uint32_t off = (uint32_t)(row * 256 + (((wn * 4 + nt) ^ g) << 4) + tp * 4);
                    *(uint32_t*)(dynsm + AT_PF + off) =
                        pack2h(acc[mt][nt][h * 2] * inv, acc[mt][nt][h * 2 + 1] * inv);
                }
            }
    }
    __syncthreads();

    // ---- phase 4: O = P @ V (single pass), ctx fp16 write ----
    {
        const int wm = wid >> 1, wn = wid & 1;
        float oac[2][4][4];
        #pragma unroll
        for (int i = 0; i < 2; ++i)
            #pragma unroll
            for (int j = 0; j < 4; ++j)
                #pragma unroll
                for (int k = 0; k < 4; ++k) oac[i][j][k] = 0.f;

        const int arow_l = lane & 15, aq_l = lane >> 4;
        const int brow_l = lane & 7,  bq_l = (lane >> 3) & 1;

        #pragma unroll
        for (int ks = 0; ks < 8; ++ks) {
            uint32_t pf[2][4], vh[4][2];
            #pragma unroll
            for (int mt = 0; mt < 2; ++mt) {
                const int row = wm * 32 + mt * 16 + arow_l;
                const uint32_t off = (uint32_t)(row * 256 + (((ks * 2 + aq_l) ^ (row & 7)) << 4));
                ldsm_x4(pf[mt], smb + AT_PF + off);
            }
            #pragma unroll
            for (int nt = 0; nt < 4; ++nt) {
                const int row = wn * 32 + nt * 8 + brow_l;
                const uint32_t off = (uint32_t)(row * 256 + (((ks * 2 + bq_l) ^ (row & 7)) << 4));
                ldsm_x2(vh[nt], smb + AT_VF + off);
            }
            #pragma unroll
            for (int mt = 0; mt < 2; ++mt)
                #pragma unroll
                for (int nt = 0; nt < 4; ++nt)
                    mma_f16(oac[mt][nt], pf[mt], vh[nt]);
        }

        #pragma unroll
        for (int mt = 0; mt < 2; ++mt)
            #pragma unroll
            for (int h = 0; h < 2; ++h) {
                const int row = wm * 32 + mt * 16 + h * 8 + g;
                const size_t rb = (m0 + row) * (size_t)GK + hh * DH_;
                #pragma unroll
                for (int nt = 0; nt < 4; ++nt) {
                    const int col = wn * 32 + nt * 8 + tp * 2;
                    *(uint32_t*)&g_Cf[rb + col] =
                        pack2h(oac[mt][nt][h * 2], oac[mt][nt][h * 2 + 1]);
                }
            }
    }
}

// ---------------------------------------------------------------------------
// Launch (6 kernels)
// ---------------------------------------------------------------------------
extern "C" void kernel_launch(void* const* d_in, const int* in_sizes, int n_in,
                              void* d_out, int out_size)
{
    (void)in_sizes; (void)n_in; (void)out_size;
    const float* x    = (const float*)d_in[0];
    const float* ln_w = (const float*)d_in[1];
    const float* ln_b = (const float*)d_in[2];
    const float* wqkv = (const float*)d_in[3];
    const float* wout = (const float*)d_in[4];
    float* out = (float*)d_out;

    void *pAf, *pWf, *pWof, *pqkv, *pCf;
    cudaGetSymbolAddress(&pAf, g_Af);
    cudaGetSymbolAddress(&pWf, g_Wf);    cudaGetSymbolAddress(&pWof, g_Wof);
    cudaGetSymbolAddress(&pqkv, g_qkv);
    cudaGetSymbolAddress(&pCf, g_Cf);

    cudaFuncSetAttribute(gemm1p_kernel,
                         cudaFuncAttributeMaxDynamicSharedMemorySize, GEMM1P_SMEM);
    cudaFuncSetAttribute(attn_kernel,
                         cudaFuncAttributeMaxDynamicSharedMemorySize, ATTN_SMEM);
    cudaFuncSetAttribute(attn_kernel,
                         cudaFuncAttributePreferredSharedMemoryCarveout, 100);

    ln_stats_kernel<<<dim3(T_ / 32, B_), 256>>>(x);
    ln_tsplit_kernel<<<dim3(T_ / 32, DIM_ / 32, B_), 256>>>(x, ln_w, ln_b);
    wsplit_kernel<<<(NW1 + NW2 + 32 * 128) / 256, 256>>>(wqkv, wout);

    gemm1p_kernel<<<dim3(3 * DIM_ / 128, MTOT / 128), 256, GEMM1P_SMEM>>>(
        (const __half*)pAf, (const __half*)pWf, (float*)pqkv, nullptr, 0);

    attn_kernel<<<B_ * NH_ * NW_, 256, ATTN_SMEM>>>((const float*)pqkv);

    gemm1p_kernel<<<dim3(DIM_ / 128, MTOT / 128), 256, GEMM1P_SMEM>>>(
        (const __half*)pCf, (const __half*)pWof, out, x, 1);
}

// round 17
// speedup vs baseline: 1.1106x; 1.1106x over previous
#include <cuda_runtime.h>
#include <cuda_bf16.h>
#include <cuda_fp16.h>
#include <math.h>
#include <cstdint>

// Problem constants
#define B_    4
#define T_    8192
#define DIM_  1024
#define NH_   16
#define DH_   64
#define WIN_  128
#define NW_   (T_ / WIN_)          // 64
#define MTOT  (B_ * T_)            // 32768
#define GK    1024                 // GEMM K

extern __shared__ char dynsm[];

// ---------------------------------------------------------------------------
// Scratch
// ---------------------------------------------------------------------------
__device__ __half  g_Af [(size_t)MTOT * GK];        // LN out (fp16 single)
__device__ __half  g_Wf [(size_t)3 * DIM_ * GK];    // w_qkv fp16 single
__device__ __half  g_Wof[(size_t)DIM_ * GK];        // w_out fp16 single
__device__ float   g_qkv[(size_t)3 * DIM_ * MTOT];  // qkv (N,M)
__device__ __half  g_Cf [(size_t)MTOT * GK];        // ctx fp16 single
__device__ float   g_mean[MTOT];
__device__ float   g_rstd[MTOT];
__device__ float2  g_cs[32 * 128];                  // RoPE table

// ---------------------------------------------------------------------------
// PTX helpers
// ---------------------------------------------------------------------------
__device__ __forceinline__ uint32_t smem_u32(const void* p) {
    uint32_t a;
    asm("{ .reg .u64 t; cvta.to.shared.u64 t, %1; cvt.u32.u64 %0, t; }" : "=r"(a) : "l"(p));
    return a;
}
__device__ __forceinline__ void cp_async16(uint32_t dst, const void* src) {
    asm volatile("cp.async.cg.shared.global [%0], [%1], 16;" :: "r"(dst), "l"(src));
}
#define CP_COMMIT()  asm volatile("cp.async.commit_group;" ::: "memory")
#define CP_WAIT(n)   asm volatile("cp.async.wait_group %0;" :: "n"(n) : "memory")

__device__ __forceinline__ void ldsm_x4(uint32_t* r, uint32_t addr) {
    asm volatile("ldmatrix.sync.aligned.m8n8.x4.shared.b16 {%0,%1,%2,%3}, [%4];"
        : "=r"(r[0]), "=r"(r[1]), "=r"(r[2]), "=r"(r[3]) : "r"(addr));
}
__device__ __forceinline__ void ldsm_x2(uint32_t* r, uint32_t addr) {
    asm volatile("ldmatrix.sync.aligned.m8n8.x2.shared.b16 {%0,%1}, [%2];"
        : "=r"(r[0]), "=r"(r[1]) : "r"(addr));
}
__device__ __forceinline__ void ldsm_x4_t(uint32_t* r, uint32_t addr) {
    asm volatile("ldmatrix.sync.aligned.m8n8.x4.trans.shared.b16 {%0,%1,%2,%3}, [%4];"
        : "=r"(r[0]), "=r"(r[1]), "=r"(r[2]), "=r"(r[3]) : "r"(addr));
}
__device__ __forceinline__ void ldsm_x2_t(uint32_t* r, uint32_t addr) {
    asm volatile("ldmatrix.sync.aligned.m8n8.x2.trans.shared.b16 {%0,%1}, [%2];"
        : "=r"(r[0]), "=r"(r[1]) : "r"(addr));
}
__device__ __forceinline__ void mma_f16(float* d, const uint32_t* a, const uint32_t* b) {
    asm volatile("mma.sync.aligned.m16n8k16.row.col.f32.f16.f16.f32 "
        "{%0,%1,%2,%3}, {%4,%5,%6,%7}, {%8,%9}, {%0,%1,%2,%3};"
        : "+f"(d[0]), "+f"(d[1]), "+f"(d[2]), "+f"(d[3])
        : "r"(a[0]), "r"(a[1]), "r"(a[2]), "r"(a[3]), "r"(b[0]), "r"(b[1]));
}

__device__ __forceinline__ uint2 pack4h(const float* v) {
    __half2 h01 = __floats2half2_rn(v[0], v[1]);
    __half2 h23 = __floats2half2_rn(v[2], v[3]);
    uint2 r; r.x = *(uint32_t*)&h01; r.y = *(uint32_t*)&h23; return r;
}
__device__ __forceinline__ uint32_t pack2h(float v0, float v1) {
    __half2 h = __floats2half2_rn(v0, v1);
    return *(uint32_t*)&h;
}

// ---------------------------------------------------------------------------
// Kernel 1: LN statistics.
// ---------------------------------------------------------------------------
__global__ __launch_bounds__(256) void ln_stats_kernel(const float* __restrict__ x)
{
    const int lane = threadIdx.x & 31;
    const int wy   = threadIdx.x >> 5;
    const int b    = blockIdx.y;
    const int t    = blockIdx.x * 32 + lane;
    const size_t xbase = (size_t)b * DIM_ * T_ + t;

    float sum = 0.f, sum2 = 0.f;
    for (int c = wy; c < DIM_; c += 8) {
        float v = x[xbase + (size_t)c * T_];
        sum += v; sum2 += v * v;
    }
    __shared__ float ps[8][32], ps2[8][32];
    ps[wy][lane] = sum; ps2[wy][lane] = sum2;
    __syncthreads();
    if (wy == 0) {
        float s = 0.f, s2 = 0.f;
        #pragma unroll
        for (int i = 0; i < 8; ++i) { s += ps[i][lane]; s2 += ps2[i][lane]; }
        float mean = s * (1.f / DIM_);
        float var  = s2 * (1.f / DIM_) - mean * mean;
        g_mean[b * T_ + t] = mean;
        g_rstd[b * T_ + t] = rsqrtf(var + 1e-5f);
    }
}

// ---------------------------------------------------------------------------
// Kernel 2: transpose + normalize + fp16 convert.
// ---------------------------------------------------------------------------
__global__ __launch_bounds__(256) void ln_tsplit_kernel(
    const float* __restrict__ x,
    const float* __restrict__ ln_w,
    const float* __restrict__ ln_b)
{
    __shared__ float tile[32][33];
    const int lane = threadIdx.x & 31;
    const int wy   = threadIdx.x >> 5;
    const int t0 = blockIdx.x * 32;
    const int c0 = blockIdx.y * 32;
    const int b  = blockIdx.z;

    #pragma unroll
    for (int jj = 0; jj < 4; ++jj) {
        const int cl = wy * 4 + jj;
        tile[cl][lane] = x[(size_t)b * DIM_ * T_ + (size_t)(c0 + cl) * T_ + t0 + lane];
    }
    __syncthreads();

    const int c = c0 + lane;
    const float lw = ln_w[c], lb = ln_b[c];
    #pragma unroll
    for (int jj = 0; jj < 4; ++jj) {
        const int r = wy * 4 + jj;
        const int m = b * T_ + t0 + r;
        const float val = (tile[lane][r] - g_mean[m]) * g_rstd[m] * lw + lb;
        g_Af[(size_t)m * GK + c] = __float2half_rn(val);
    }
}

// ---------------------------------------------------------------------------
// Kernel 3: weight fp16 conversion + RoPE table fill.
// ---------------------------------------------------------------------------
#define NW1 (3 * DIM_ * GK)
#define NW2 (DIM_ * GK)
#define RKC 0.4152410118609203f   // log2(10000)/32

__global__ __launch_bounds__(256) void wsplit_kernel(
    const float* __restrict__ w1, const float* __restrict__ w2)
{
    const int i = blockIdx.x * 256 + threadIdx.x;
    if (i < NW1) {
        g_Wf[i] = __float2half_rn(w1[i]);
    } else if (i < NW1 + NW2) {
        g_Wof[i - NW1] = __float2half_rn(w2[i - NW1]);
    } else {
        const int e = i - (NW1 + NW2);
        const int d = e >> 7, tok = e & 127;
        const float ang = (float)tok * exp2f(-(float)d * RKC);
        float s, c;
        sincosf(ang, &s, &c);
        g_cs[e] = make_float2(c, s);
    }
}

// ---------------------------------------------------------------------------
// Kernel 4: single-pass fp16 GEMM, round-15 double-buffered loop (load
// issued BEFORE CP_WAIT — the ordering that measured 540us / tensor 63%).
// ---------------------------------------------------------------------------
#define KC 32
#define NCHUNK (GK / KC)
#define STG1 16384                  // A 8K | B 8K
#define GEMM1P_SMEM (128 * 132 * 4) // C staging dominates (67584)

__device__ __forceinline__ void load_stage_1p(
    const __half* __restrict__ A, const __half* __restrict__ Bw,
    uint32_t sbase, int m0, int n0, int k0, int tid)
{
    #pragma unroll
    for (int it = 0; it < 2; ++it) {
        const int o = it * 256 + tid;
        const int r = o >> 2, q = o & 3;
        const uint32_t sw = (uint32_t)(r * 64 + ((q ^ ((r >> 1) & 3)) << 4));
        const size_t ga = (size_t)(m0 + r) * GK + k0 + q * 8;
        const size_t gb = (size_t)(n0 + r) * GK + k0 + q * 8;
        cp_async16(sbase + sw,        A  + ga);
        cp_async16(sbase + 8192 + sw, Bw + gb);
    }
}

__global__ __launch_bounds__(256) void gemm1p_kernel(
    const __half* __restrict__ A, const __half* __restrict__ Bw,
    float* __restrict__ C, const float* __restrict__ resid, int mode)
{
    const uint32_t smb = smem_u32(dynsm);
    const int tid  = threadIdx.x;
    const int wid  = tid >> 5;
    const int lane = tid & 31;
    const int wm = wid >> 2;
    const int wn = wid & 3;
    const int n0 = blockIdx.x * 128;
    const int m0 = blockIdx.y * 128;

    float acc[4][4][4];
    #pragma unroll
    for (int i = 0; i < 4; ++i)
        #pragma unroll
        for (int j = 0; j < 4; ++j)
            #pragma unroll
            for (int k = 0; k < 4; ++k) acc[i][j][k] = 0.f;

    load_stage_1p(A, Bw, smb, m0, n0, 0, tid);
    CP_COMMIT();

    const int arow_l = (lane & 15);
    const int aq_l   = lane >> 4;
    const int brow_l = (lane & 7);
    const int bq_l   = (lane >> 3) & 1;

    for (int i = 0; i < NCHUNK; ++i) {
        const int buf = i & 1;
        if (i + 1 < NCHUNK) {
            load_stage_1p(A, Bw, smb + (buf ^ 1) * STG1, m0, n0, (i + 1) * KC, tid);
            CP_COMMIT();
            CP_WAIT(1);
        } else {
            CP_WAIT(0);
        }
        __syncthreads();

        const uint32_t sA = smb + buf * STG1;
        #pragma unroll
        for (int ks = 0; ks < 2; ++ks) {
            uint32_t af[4][4], bh[4][2];
            #pragma unroll
            for (int mt = 0; mt < 4; ++mt) {
                const int row = wm * 64 + mt * 16 + arow_l;
                const int q   = ks * 2 + aq_l;
                ldsm_x4(af[mt], sA + row * 64 + ((q ^ ((row >> 1) & 3)) << 4));
            }
            #pragma unroll
            for (int nt = 0; nt < 4; ++nt) {
                const int row = wn * 32 + nt * 8 + brow_l;
                const int q   = ks * 2 + bq_l;
                ldsm_x2(bh[nt], sA + 8192 + row * 64 + ((q ^ ((row >> 1) & 3)) << 4));
            }
            #pragma unroll
            for (int mt = 0; mt < 4; ++mt)
                #pragma unroll
                for (int nt = 0; nt < 4; ++nt)
                    mma_f16(acc[mt][nt], af[mt], bh[nt]);
        }
        __syncthreads();
    }

    float* Cs = (float*)dynsm;
    const int g  = lane >> 2;
    const int tp = lane & 3;
    #pragma unroll
    for (int mt = 0; mt < 4; ++mt)
        #pragma unroll
        for (int nt = 0; nt < 4; ++nt) {
            const int mb = wm * 64 + mt * 16;
            const int nb = wn * 32 + nt * 8;
            Cs[(nb + 2 * tp)     * 132 + mb + g]     = acc[mt][nt][0];
            Cs[(nb + 2 * tp + 1) * 132 + mb + g]     = acc[mt][nt][1];
            Cs[(nb + 2 * tp)     * 132 + mb + g + 8] = acc[mt][nt][2];
            Cs[(nb + 2 * tp + 1) * 132 + mb + g + 8] = acc[mt][nt][3];
        }
    __syncthreads();

    if (mode == 0) {
        for (int o = tid; o < 128 * 128; o += 256) {
            const int r = o >> 7, c = o & 127;
            C[(size_t)(n0 + r) * MTOT + m0 + c] = Cs[r * 132 + c];
        }
    } else {
        const int b = m0 >> 13;
        const int t = m0 & (T_ - 1);
        const size_t base = (size_t)b * DIM_ * T_ + t;
        for (int o = tid; o < 128 * 128; o += 256) {
            const int r = o >> 7, c = o & 127;
            const size_t idx = base + (size_t)(n0 + r) * T_ + c;
            C[idx] = Cs[r * 132 + c] + resid[idx];
        }
    }
}

// ---------------------------------------------------------------------------
// Kernel 5: windowed attention, single-pass fp16 both MMAs (round-16 version).
// ---------------------------------------------------------------------------
#define AT_QF  0
#define AT_KF  16384
#define AT_PF  0
#define AT_VF  32768
#define AT_PMAX 49152
#define AT_PSUM 51200
#define ATTN_SMEM 53248

__global__ __launch_bounds__(256, 2) void attn_kernel(const float* __restrict__ qkv)
{
    const int blk = blockIdx.x;
    const int w   = blk & (NW_ - 1);
    const int hh  = (blk >> 6) & (NH_ - 1);
    const int b   = blk >> 10;
    const size_t M  = MTOT;
    const size_t m0 = (size_t)b * T_ + (size_t)w * WIN_;
    const int tid  = threadIdx.x;
    const int wid  = tid >> 5;
    const int lane = tid & 31;

    const uint32_t smb = smem_u32(dynsm);
    float* pmax = (float*)(dynsm + AT_PMAX);
    float* psum = (float*)(dynsm + AT_PSUM);

    // ---- phase 1: global load + RoPE; all fp16 single ----
    for (int it = tid; it < 512; it += 256) {
        const int d = it >> 4, ch = it & 15;
        const float* qp = qkv + (size_t)(hh * 64 + d) * M + m0 + ch * 8;
        float ql[8], qh[8], kl[8], kh[8], v0[8], v1[8];
        *(float4*)&ql[0] = *(const float4*)&qp[0];
        *(float4*)&ql[4] = *(const float4*)&qp[4];
        *(float4*)&qh[0] = *(const float4*)&qp[32 * M];
        *(float4*)&qh[4] = *(const float4*)&qp[32 * M + 4];
        const float* kp = qp + (size_t)DIM_ * M;
        *(float4*)&kl[0] = *(const float4*)&kp[0];
        *(float4*)&kl[4] = *(const float4*)&kp[4];
        *(float4*)&kh[0] = *(const float4*)&kp[32 * M];
        *(float4*)&kh[4] = *(const float4*)&kp[32 * M + 4];
        const float* vp = qp + (size_t)(2 * DIM_) * M;
        *(float4*)&v0[0] = *(const float4*)&vp[0];
        *(float4*)&v0[4] = *(const float4*)&vp[4];
        *(float4*)&v1[0] = *(const float4*)&vp[32 * M];
        *(float4*)&v1[4] = *(const float4*)&vp[32 * M + 4];

        float qnl[8], qnu[8], knl[8], knu[8];
        #pragma unroll
        for (int j = 0; j < 8; ++j) {
            const float2 cs = g_cs[d * 128 + ch * 8 + j];
            qnl[j] = ql[j] * cs.x - qh[j] * cs.y;
            qnu[j] = qh[j] * cs.x + ql[j] * cs.y;
            knl[j] = kl[j] * cs.x - kh[j] * cs.y;
            knu[j] = kh[j] * cs.x + kl[j] * cs.y;
        }
        const uint32_t swd  = (uint32_t)(d * 256 + ((ch ^ (d & 7)) << 4));
        const uint32_t swd2 = swd + 32 * 256;
        uint2 a0, a1;
        a0 = pack4h(&qnl[0]); a1 = pack4h(&qnl[4]);
        *(uint4*)(dynsm + AT_QF + swd) = make_uint4(a0.x, a0.y, a1.x, a1.y);
        a0 = pack4h(&qnu[0]); a1 = pack4h(&qnu[4]);
        *(uint4*)(dynsm + AT_QF + swd2) = make_uint4(a0.x, a0.y, a1.x, a1.y);
        a0 = pack4h(&knl[0]); a1 = pack4h(&knl[4]);
        *(uint4*)(dynsm + AT_KF + swd) = make_uint4(a0.x, a0.y, a1.x, a1.y);
        a0 = pack4h(&knu[0]); a1 = pack4h(&knu[4]);
        *(uint4*)(dynsm + AT_KF + swd2) = make_uint4(a0.x, a0.y, a1.x, a1.y);
        a0 = pack4h(&v0[0]); a1 = pack4h(&v0[4]);
        *(uint4*)(dynsm + AT_VF + swd) = make_uint4(a0.x, a0.y, a1.x, a1.y);
        a0 = pack4h(&v1[0]); a1 = pack4h(&v1[4]);
        *(uint4*)(dynsm + AT_VF + swd2) = make_uint4(a0.x, a0.y, a1.x, a1.y);
    }
    __syncthreads();

    // ---- phase 2: S = Q@K^T via trans-ldmatrix (single pass) ----
    const int g  = lane >> 2;
    const int tp = lane & 3;
    float acc[4][4][4];
    {
        const int wm = wid >> 2, wn = wid & 3;
        #pragma unroll
        for (int i = 0; i < 4; ++i)
            #pragma unroll
            for (int j = 0; j < 4; ++j)
                #pragma unroll
                for (int k = 0; k < 4; ++k) acc[i][j][k] = 0.f;

        const int Lg   = lane & 7;
        const int grpA = lane >> 3;
        const int aoff = ((grpA & 2) << 2) + Lg;
        const int acb  = wm * 8 + (grpA & 1);
        const int bg   = (lane >> 3) & 1;

        #pragma unroll
        for (int ks = 0; ks < 4; ++ks) {
            uint32_t af[4][4], bh[4][2];
            const uint32_t arow = (uint32_t)((ks * 16 + aoff) * 256);
            #pragma unroll
            for (int mt = 0; mt < 4; ++mt)
                ldsm_x4_t(af[mt], smb + AT_QF + arow + (((acb + mt * 2) ^ Lg) << 4));
            const uint32_t brow = (uint32_t)((ks * 16 + bg * 8 + Lg) * 256);
            #pragma unroll
            for (int nt = 0; nt < 4; ++nt)
                ldsm_x2_t(bh[nt], smb + AT_KF + brow + (((wn * 4 + nt) ^ Lg) << 4));
            #pragma unroll
            for (int mt = 0; mt < 4; ++mt)
                #pragma unroll
                for (int nt = 0; nt < 4; ++nt)
                    mma_f16(acc[mt][nt], af[mt], bh[nt]);
        }

        // ---- phase 3: softmax from registers ----
        #pragma unroll
        for (int mt = 0; mt < 4; ++mt)
            #pragma unroll
            for (int h = 0; h < 2; ++h) {
                float mx = -1e30f;
                #pragma unroll
                for (int nt = 0; nt < 4; ++nt)
                    mx = fmaxf(mx, fmaxf(acc[mt][nt][h * 2], acc[mt][nt][h * 2 + 1]));
                mx = fmaxf(mx, __shfl_xor_sync(0xffffffffu, mx, 1));
                mx = fmaxf(mx, __shfl_xor_sync(0xffffffffu, mx, 2));
                if (tp == 0)
                    pmax[(wm * 64 + mt * 16 + h * 8 + g) * 4 + wn] = mx;
            }
        __syncthreads();
        #pragma unroll
        for (int mt = 0; mt < 4; ++mt)
            #pragma unroll
            for (int h = 0; h < 2; ++h) {
                const int row = wm * 64 + mt * 16 + h * 8 + g;
                const float4 pm = *(const float4*)&pmax[row * 4];
                const float Mx = fmaxf(fmaxf(pm.x, pm.y), fmaxf(pm.z, pm.w));
                float s = 0.f;
                #pragma unroll
                for (int nt = 0; nt < 4; ++nt) {
                    float e0 = __expf((acc[mt][nt][h * 2]     - Mx) * 0.125f);
                    float e1 = __expf((acc[mt][nt][h * 2 + 1] - Mx) * 0.125f);
                    acc[mt][nt][h * 2]     = e0;
                    acc[mt][nt][h * 2 + 1] = e1;
                    s += e0 + e1;
                }
                s += __shfl_xor_sync(0xffffffffu, s, 1);
                s += __shfl_xor_sync(0xffffffffu, s, 2);
                if (tp == 0)
                    psum[(wm * 64 + mt * 16 + h * 8 + g) * 4 + wn] = s;
            }
        __syncthreads();
        #pragma unroll
        for (int mt = 0; mt < 4; ++mt)
            #pragma unroll
            for (int h = 0; h < 2; ++h) {
                const int row = wm * 64 + mt * 16 + h * 8 + g;
                const float4 sm4 = *(const float4*)&psum[row * 4];
                const float inv = 1.f / (sm4.x + sm4.y + sm4.z + sm4.w);
                #pragma unroll
                for (int nt = 0; nt < 4; ++nt) {
                    const uint32_t off = (uint32_t)(row * 256 + (((wn * 4 + nt) ^ g) << 4) + tp * 4);
                    *(uint32_t*)(dynsm + AT_PF + off) =
                        pack2h(acc[mt][nt][h * 2] * inv, acc[mt][nt][h * 2 + 1] * inv);
                }
            }
    }
    __syncthreads();

    // ---- phase 4: O = P @ V (single pass), ctx fp16 write ----
    {
        const int wm = wid >> 1, wn = wid & 1;
        float oac[2][4][4];
        #pragma unroll
        for (int i = 0; i < 2; ++i)
            #pragma unroll
            for (int j = 0; j < 4; ++j)
                #pragma unroll
                for (int k = 0; k < 4; ++k) oac[i][j][k] = 0.f;

        const int arow_l = lane & 15, aq_l = lane >> 4;
        const int brow_l = lane & 7,  bq_l = (lane >> 3) & 1;

        #pragma unroll
        for (int ks = 0; ks < 8; ++ks) {
            uint32_t pf[2][4], vh[4][2];
            #pragma unroll
            for (int mt = 0; mt < 2; ++mt) {
                const int row = wm * 32 + mt * 16 + arow_l;
                const uint32_t off = (uint32_t)(row * 256 + (((ks * 2 + aq_l) ^ (row & 7)) << 4));
                ldsm_x4(pf[mt], smb + AT_PF + off);
            }
            #pragma unroll
            for (int nt = 0; nt < 4; ++nt) {
                const int row = wn * 32 + nt * 8 + brow_l;
                const uint32_t off = (uint32_t)(row * 256 + (((ks * 2 + bq_l) ^ (row & 7)) << 4));
                ldsm_x2(vh[nt], smb + AT_VF + off);
            }
            #pragma unroll
            for (int mt = 0; mt < 2; ++mt)
                #pragma unroll
                for (int nt = 0; nt < 4; ++nt)
                    mma_f16(oac[mt][nt], pf[mt], vh[nt]);
        }

        #pragma unroll
        for (int mt = 0; mt < 2; ++mt)
            #pragma unroll
            for (int h = 0; h < 2; ++h) {
                const int row = wm * 32 + mt * 16 + h * 8 + g;
                const size_t rb = (m0 + row) * (size_t)GK + hh * DH_;
                #pragma unroll
                for (int nt = 0; nt < 4; ++nt) {
                    const int col = wn * 32 + nt * 8 + tp * 2;
                    *(uint32_t*)&g_Cf[rb + col] =
                        pack2h(oac[mt][nt][h * 2], oac[mt][nt][h * 2 + 1]);
                }
            }
    }
}

// ---------------------------------------------------------------------------
// Launch (6 kernels)
// ---------------------------------------------------------------------------
extern "C" void kernel_launch(void* const* d_in, const int* in_sizes, int n_in,
                              void* d_out, int out_size)
{
    (void)in_sizes; (void)n_in; (void)out_size;
    const float* x    = (const float*)d_in[0];
    const float* ln_w = (const float*)d_in[1];
    const float* ln_b = (const float*)d_in[2];
    const float* wqkv = (const float*)d_in[3];
    const float* wout = (const float*)d_in[4];
    float* out = (float*)d_out;

    void *pAf, *pWf, *pWof, *pqkv, *pCf;
    cudaGetSymbolAddress(&pAf, g_Af);
    cudaGetSymbolAddress(&pWf, g_Wf);    cudaGetSymbolAddress(&pWof, g_Wof);
    cudaGetSymbolAddress(&pqkv, g_qkv);
    cudaGetSymbolAddress(&pCf, g_Cf);

    cudaFuncSetAttribute(gemm1p_kernel,
                         cudaFuncAttributeMaxDynamicSharedMemorySize, GEMM1P_SMEM);
    cudaFuncSetAttribute(attn_kernel,
                         cudaFuncAttributeMaxDynamicSharedMemorySize, ATTN_SMEM);
    cudaFuncSetAttribute(attn_kernel,
                         cudaFuncAttributePreferredSharedMemoryCarveout, 100);

    ln_stats_kernel<<<dim3(T_ / 32, B_), 256>>>(x);
    ln_tsplit_kernel<<<dim3(T_ / 32, DIM_ / 32, B_), 256>>>(x, ln_w, ln_b);
    wsplit_kernel<<<(NW1 + NW2 + 32 * 128) / 256, 256>>>(wqkv, wout);

    gemm1p_kernel<<<dim3(3 * DIM_ / 128, MTOT / 128), 256, GEMM1P_SMEM>>>(
        (const __half*)pAf, (const __half*)pWf, (float*)pqkv, nullptr, 0);

    attn_kernel<<<B_ * NH_ * NW_, 256, ATTN_SMEM>>>((const float*)pqkv);

    gemm1p_kernel<<<dim3(DIM_ / 128, MTOT / 128), 256, GEMM1P_SMEM>>>(
        (const __half*)pCf, (const __half*)pWof, out, x, 1);
}